// round 1
// baseline (speedup 1.0000x reference)
#include <cuda_runtime.h>
#include <mma.h>

using namespace nvcuda;

// Problem constants
#define BATCH 8
#define SEQ   2048
#define DIM   1024
#define DOUT  1024
#define MTOT  (BATCH * SEQ)        // 16384

// GEMM tiling
#define BM 128
#define BN 128
#define BK 16
#define BKP 20     // BK + 4  (80B stride, 16B-multiple)
#define BNP 132    // BN + 4  (528B stride, 16B-multiple)

// Scratch (allocation-free rule: __device__ globals)
__device__ float g_q[MTOT * DIM];        // 64 MB
__device__ float g_k[MTOT * DIM];        // 64 MB
__device__ float g_v[MTOT * DOUT];       // 64 MB
__device__ float g_s[BATCH * SEQ * SEQ]; // 128 MB

// ---------------------------------------------------------------------------
// TF32 WMMA GEMM:  C[M,N] = scale * (A[M,K] @ B) + bias
//   TRANSB=false: B is [K,N] row-major
//   TRANSB=true : B is [N,K] row-major (i.e. C = A @ B^T)
// Batched via blockIdx.z with element strides sA/sB/sC.
// All dims are multiples of the tile sizes (guaranteed by this problem).
// ---------------------------------------------------------------------------
template <bool TRANSB>
__global__ __launch_bounds__(256)
void gemm_tf32(const float* __restrict__ Ab, const float* __restrict__ Bb,
               const float* __restrict__ bias, float* __restrict__ Cb,
               int K, int lda, int ldb, int ldc,
               long long sA, long long sB, long long sC, float scale)
{
    __shared__ float As[BM * BKP];                 // 10240 B
    __shared__ float Bs[BM * BKP];                 // covers both layouts (2560 >= 16*132)
    __shared__ float BiasT[16 * BNP];              // 8448 B

    const float* A = Ab + (long long)blockIdx.z * sA;
    const float* B = Bb + (long long)blockIdx.z * sB;
    float*       C = Cb + (long long)blockIdx.z * sC;

    const int m0 = blockIdx.y * BM;
    const int n0 = blockIdx.x * BN;
    const int t  = threadIdx.x;
    const int warp = t >> 5;
    const int wm = warp >> 2;   // 0..1  (64-row slab)
    const int wn = warp & 3;    // 0..3  (32-col slab)

    wmma::fragment<wmma::accumulator, 16, 16, 8, float> acc[4][2];

    if (bias != nullptr) {
        for (int i = t; i < 16 * BN; i += 256) {
            int r = i >> 7, c = i & 127;
            BiasT[r * BNP + c] = bias[n0 + c];
        }
        __syncthreads();
        #pragma unroll
        for (int mi = 0; mi < 4; mi++)
            #pragma unroll
            for (int nj = 0; nj < 2; nj++)
                wmma::load_matrix_sync(acc[mi][nj], &BiasT[wn * 32 + nj * 16],
                                       BNP, wmma::mem_row_major);
    } else {
        #pragma unroll
        for (int mi = 0; mi < 4; mi++)
            #pragma unroll
            for (int nj = 0; nj < 2; nj++)
                wmma::fill_fragment(acc[mi][nj], 0.0f);
    }

    const int ar = t >> 2;          // 0..63
    const int ac = (t & 3) << 2;    // 0,4,8,12

    for (int k0 = 0; k0 < K; k0 += BK) {
        // --- A tile: 128 x 16, float4 per thread x2 ---
        {
            float4 v0 = *(const float4*)&A[(long long)(m0 + ar)      * lda + k0 + ac];
            float4 v1 = *(const float4*)&A[(long long)(m0 + ar + 64) * lda + k0 + ac];
            *(float4*)&As[ar        * BKP + ac] = v0;
            *(float4*)&As[(ar + 64) * BKP + ac] = v1;
        }
        // --- B tile ---
        if (TRANSB) {
            // source rows are N, cols are K: natural copy, store [BN][BKP]
            float4 v0 = *(const float4*)&B[(long long)(n0 + ar)      * ldb + k0 + ac];
            float4 v1 = *(const float4*)&B[(long long)(n0 + ar + 64) * ldb + k0 + ac];
            *(float4*)&Bs[ar        * BKP + ac] = v0;
            *(float4*)&Bs[(ar + 64) * BKP + ac] = v1;
        } else {
            // source rows are K, cols are N: store [BK][BNP]
            int br = t >> 5;          // 0..7
            int bc = (t & 31) << 2;   // 0..124
            float4 v0 = *(const float4*)&B[(long long)(k0 + br)     * ldb + n0 + bc];
            float4 v1 = *(const float4*)&B[(long long)(k0 + br + 8) * ldb + n0 + bc];
            *(float4*)&Bs[br       * BNP + bc] = v0;
            *(float4*)&Bs[(br + 8) * BNP + bc] = v1;
        }
        __syncthreads();

        #pragma unroll
        for (int kk = 0; kk < BK; kk += 8) {
            wmma::fragment<wmma::matrix_a, 16, 16, 8, wmma::precision::tf32,
                           wmma::row_major> af[4];
            #pragma unroll
            for (int mi = 0; mi < 4; mi++) {
                wmma::load_matrix_sync(af[mi], &As[(wm * 64 + mi * 16) * BKP + kk], BKP);
                #pragma unroll
                for (int e = 0; e < af[mi].num_elements; e++)
                    af[mi].x[e] = wmma::__float_to_tf32(af[mi].x[e]);
            }
            #pragma unroll
            for (int nj = 0; nj < 2; nj++) {
                if constexpr (TRANSB) {
                    wmma::fragment<wmma::matrix_b, 16, 16, 8, wmma::precision::tf32,
                                   wmma::col_major> bf;
                    wmma::load_matrix_sync(bf, &Bs[(wn * 32 + nj * 16) * BKP + kk], BKP);
                    #pragma unroll
                    for (int e = 0; e < bf.num_elements; e++)
                        bf.x[e] = wmma::__float_to_tf32(bf.x[e]);
                    #pragma unroll
                    for (int mi = 0; mi < 4; mi++)
                        wmma::mma_sync(acc[mi][nj], af[mi], bf, acc[mi][nj]);
                } else {
                    wmma::fragment<wmma::matrix_b, 16, 16, 8, wmma::precision::tf32,
                                   wmma::row_major> bf;
                    wmma::load_matrix_sync(bf, &Bs[kk * BNP + wn * 32 + nj * 16], BNP);
                    #pragma unroll
                    for (int e = 0; e < bf.num_elements; e++)
                        bf.x[e] = wmma::__float_to_tf32(bf.x[e]);
                    #pragma unroll
                    for (int mi = 0; mi < 4; mi++)
                        wmma::mma_sync(acc[mi][nj], af[mi], bf, acc[mi][nj]);
                }
            }
        }
        __syncthreads();
    }

    // Epilogue: scale + store
    #pragma unroll
    for (int mi = 0; mi < 4; mi++) {
        #pragma unroll
        for (int nj = 0; nj < 2; nj++) {
            if (scale != 1.0f) {
                #pragma unroll
                for (int e = 0; e < acc[mi][nj].num_elements; e++)
                    acc[mi][nj].x[e] *= scale;
            }
            wmma::store_matrix_sync(
                &C[(long long)(m0 + wm * 64 + mi * 16) * ldc + n0 + wn * 32 + nj * 16],
                acc[mi][nj], ldc, wmma::mem_row_major);
        }
    }
}

// ---------------------------------------------------------------------------
// Row softmax over 2048-wide rows, one block (256 threads) per row.
// ---------------------------------------------------------------------------
__global__ __launch_bounds__(256)
void softmax2048(float* __restrict__ S)
{
    float* p = S + (long long)blockIdx.x * SEQ;
    const int t = threadIdx.x;

    float4 v0 = *(const float4*)&p[t * 4];
    float4 v1 = *(const float4*)&p[1024 + t * 4];

    float m = fmaxf(fmaxf(fmaxf(v0.x, v0.y), fmaxf(v0.z, v0.w)),
                    fmaxf(fmaxf(v1.x, v1.y), fmaxf(v1.z, v1.w)));
    #pragma unroll
    for (int o = 16; o > 0; o >>= 1)
        m = fmaxf(m, __shfl_xor_sync(0xffffffffu, m, o));

    __shared__ float sm[8], ss[8];
    if ((t & 31) == 0) sm[t >> 5] = m;
    __syncthreads();
    m = fmaxf(fmaxf(fmaxf(sm[0], sm[1]), fmaxf(sm[2], sm[3])),
              fmaxf(fmaxf(sm[4], sm[5]), fmaxf(sm[6], sm[7])));

    v0.x = __expf(v0.x - m); v0.y = __expf(v0.y - m);
    v0.z = __expf(v0.z - m); v0.w = __expf(v0.w - m);
    v1.x = __expf(v1.x - m); v1.y = __expf(v1.y - m);
    v1.z = __expf(v1.z - m); v1.w = __expf(v1.w - m);

    float s = (v0.x + v0.y + v0.z + v0.w) + (v1.x + v1.y + v1.z + v1.w);
    #pragma unroll
    for (int o = 16; o > 0; o >>= 1)
        s += __shfl_xor_sync(0xffffffffu, s, o);
    if ((t & 31) == 0) ss[t >> 5] = s;
    __syncthreads();
    s = (ss[0] + ss[1] + ss[2] + ss[3]) + (ss[4] + ss[5] + ss[6] + ss[7]);

    float inv = 1.0f / s;
    v0.x *= inv; v0.y *= inv; v0.z *= inv; v0.w *= inv;
    v1.x *= inv; v1.y *= inv; v1.z *= inv; v1.w *= inv;

    *(float4*)&p[t * 4]        = v0;
    *(float4*)&p[1024 + t * 4] = v1;
}

// ---------------------------------------------------------------------------
extern "C" void kernel_launch(void* const* d_in, const int* in_sizes, int n_in,
                              void* d_out, int out_size)
{
    const float* X  = (const float*)d_in[0];
    const float* Wq = (const float*)d_in[1];
    const float* bq = (const float*)d_in[2];
    const float* Wk = (const float*)d_in[3];
    const float* bk = (const float*)d_in[4];
    const float* Wv = (const float*)d_in[5];
    const float* bv = (const float*)d_in[6];
    float* out = (float*)d_out;

    float *q, *k, *v, *s;
    cudaGetSymbolAddress((void**)&q, g_q);
    cudaGetSymbolAddress((void**)&k, g_k);
    cudaGetSymbolAddress((void**)&v, g_v);
    cudaGetSymbolAddress((void**)&s, g_s);

    const long long TD = (long long)SEQ * DIM;   // 2097152
    const long long TT = (long long)SEQ * SEQ;   // 4194304

    // Phase 1: Q/K/V projections  C[16384,1024] = X @ W + b
    {
        dim3 grid(DIM / BN, MTOT / BM, 1);  // (8, 128, 1)
        gemm_tf32<false><<<grid, 256>>>(X, Wq, bq, q, DIM, DIM, DIM, DIM, 0, 0, 0, 1.0f);
        gemm_tf32<false><<<grid, 256>>>(X, Wk, bk, k, DIM, DIM, DIM, DIM, 0, 0, 0, 1.0f);
        gemm_tf32<false><<<grid, 256>>>(X, Wv, bv, v, DIM, DIM, DIM, DIM, 0, 0, 0, 1.0f);
    }

    // Phase 2: scores = (Q @ K^T) / sqrt(D), batched over 8
    {
        dim3 grid(SEQ / BN, SEQ / BM, BATCH);  // (16, 16, 8)
        gemm_tf32<true><<<grid, 256>>>(q, k, nullptr, s, DIM, DIM, DIM, SEQ,
                                       TD, TD, TT, 0.03125f);
    }

    // Phase 3: row softmax over all B*T rows
    softmax2048<<<MTOT, 256>>>(s);

    // Phase 4: out = P @ V, batched over 8
    {
        dim3 grid(DOUT / BN, SEQ / BM, BATCH);  // (8, 16, 8)
        gemm_tf32<false><<<grid, 256>>>(s, v, nullptr, out, SEQ, SEQ, DOUT, DOUT,
                                        TT, TD, TD, 1.0f);
    }
}

// round 3
// speedup vs baseline: 1.4474x; 1.4474x over previous
#include <cuda_runtime.h>
#include <cstdint>
#include <mma.h>

using namespace nvcuda;

// Problem constants
#define BATCH 8
#define SEQ   2048
#define DIM   1024
#define MTOT  (BATCH * SEQ)        // 16384

// GEMM tiling
#define BM 128
#define BN 128
#define BK 32
#define AKP 36     // A tile row stride (floats), 16B multiple
#define BKP 36     // B (trans) tile row stride
#define BNP 132    // B (non-trans) tile row stride
#define BUF_ELEMS 4608                  // 128*36 floats, covers all tile layouts
#define SMEM_BYTES (4 * BUF_ELEMS * 4)  // 2xA + 2xB double buffers = 73728 B

// Scratch (__device__ globals; allocation-free rule)
__device__ float g_q[MTOT * DIM];          // 64 MB
__device__ float g_k[MTOT * DIM];          // 64 MB
__device__ float g_v[MTOT * DIM];          // 64 MB
__device__ float g_s[BATCH * SEQ * SEQ];   // 128 MB (Xc/Wc during phase1, scores after)

__device__ __forceinline__ float to_tf32(float x) {
    float y;
    asm("cvt.rna.tf32.f32 %0, %1;" : "=f"(y) : "f"(x));
    return y;
}

__device__ __forceinline__ void cp16(void* smem, const void* gmem) {
    unsigned int s = (unsigned int)__cvta_generic_to_shared(smem);
    asm volatile("cp.async.cg.shared.global [%0], [%1], 16;\n" :: "r"(s), "l"(gmem));
}
#define CP_COMMIT() asm volatile("cp.async.commit_group;\n")

// ---------------------------------------------------------------------------
// TF32 WMMA GEMM, cp.async double-buffered. Inputs must be pre-rounded to tf32.
//   C[M,N] = scale * (A @ B(^T)) + bias ; ROUND_OUT rounds stores to tf32.
// ---------------------------------------------------------------------------
template <bool TRANSB, bool ROUND_OUT>
__global__ __launch_bounds__(256, 2)
void gemm_tf32(const float* __restrict__ Ab, const float* __restrict__ Bb,
               const float* __restrict__ bias, float* __restrict__ Cb,
               int K, int lda, int ldb, int ldc,
               long long sA, long long sB, long long sC, float scale)
{
    extern __shared__ float sh[];
    float* As0 = sh;
    float* As1 = sh + BUF_ELEMS;
    float* Bs0 = sh + 2 * BUF_ELEMS;
    float* Bs1 = sh + 3 * BUF_ELEMS;
    __shared__ float BiasT[16 * BNP];

    const float* A = Ab + (long long)blockIdx.z * sA;
    const float* B = Bb + (long long)blockIdx.z * sB;
    float*       C = Cb + (long long)blockIdx.z * sC;

    const int m0 = blockIdx.y * BM;
    const int n0 = blockIdx.x * BN;
    const int t  = threadIdx.x;
    const int warp = t >> 5;
    const int wm = warp >> 2;   // 0..1 (64-row slab)
    const int wn = warp & 3;    // 0..3 (32-col slab)

    wmma::fragment<wmma::accumulator, 16, 16, 8, float> acc[4][2];

    if (bias != nullptr) {
        for (int i = t; i < 16 * BN; i += 256) {
            int r = i >> 7, c = i & 127;
            BiasT[r * BNP + c] = bias[n0 + c];
        }
        __syncthreads();
        #pragma unroll
        for (int mi = 0; mi < 4; mi++)
            #pragma unroll
            for (int nj = 0; nj < 2; nj++)
                wmma::load_matrix_sync(acc[mi][nj], &BiasT[wn * 32 + nj * 16],
                                       BNP, wmma::mem_row_major);
        __syncthreads();
    } else {
        #pragma unroll
        for (int mi = 0; mi < 4; mi++)
            #pragma unroll
            for (int nj = 0; nj < 2; nj++)
                wmma::fill_fragment(acc[mi][nj], 0.0f);
    }

    // Stage one 128x32 A tile + B tile into buffer via cp.async
    auto stage = [&](int k0, float* Ad, float* Bd) {
        #pragma unroll
        for (int j = 0; j < 4; j++) {
            int c  = t + 256 * j;          // 0..1023
            int r  = c >> 3;               // 0..127
            int cc = (c & 7) << 2;         // 0,4,..,28
            cp16(&Ad[r * AKP + cc], &A[(long long)(m0 + r) * lda + k0 + cc]);
        }
        if (TRANSB) {
            #pragma unroll
            for (int j = 0; j < 4; j++) {
                int c  = t + 256 * j;
                int r  = c >> 3;
                int cc = (c & 7) << 2;
                cp16(&Bd[r * BKP + cc], &B[(long long)(n0 + r) * ldb + k0 + cc]);
            }
        } else {
            #pragma unroll
            for (int j = 0; j < 4; j++) {
                int c  = t + 256 * j;
                int r  = c >> 5;               // 0..31
                int cc = (c & 31) << 2;        // 0..124
                cp16(&Bd[r * BNP + cc], &B[(long long)(k0 + r) * ldb + n0 + cc]);
            }
        }
    };

    const int nchunk = K / BK;
    stage(0, As0, Bs0);
    CP_COMMIT();

    int cur = 0;
    for (int i = 0; i < nchunk; i++) {
        float* Ac = cur ? As1 : As0;
        float* Bc = cur ? Bs1 : Bs0;
        if (i + 1 < nchunk) {
            stage((i + 1) * BK, cur ? As0 : As1, cur ? Bs0 : Bs1);
            CP_COMMIT();
            asm volatile("cp.async.wait_group 1;\n");
        } else {
            asm volatile("cp.async.wait_group 0;\n");
        }
        __syncthreads();

        #pragma unroll
        for (int kk = 0; kk < BK; kk += 8) {
            wmma::fragment<wmma::matrix_a, 16, 16, 8, wmma::precision::tf32,
                           wmma::row_major> af[4];
            #pragma unroll
            for (int mi = 0; mi < 4; mi++)
                wmma::load_matrix_sync(af[mi], &Ac[(wm * 64 + mi * 16) * AKP + kk], AKP);

            #pragma unroll
            for (int nj = 0; nj < 2; nj++) {
                if constexpr (TRANSB) {
                    wmma::fragment<wmma::matrix_b, 16, 16, 8, wmma::precision::tf32,
                                   wmma::col_major> bf;
                    wmma::load_matrix_sync(bf, &Bc[(wn * 32 + nj * 16) * BKP + kk], BKP);
                    #pragma unroll
                    for (int mi = 0; mi < 4; mi++)
                        wmma::mma_sync(acc[mi][nj], af[mi], bf, acc[mi][nj]);
                } else {
                    wmma::fragment<wmma::matrix_b, 16, 16, 8, wmma::precision::tf32,
                                   wmma::row_major> bf;
                    wmma::load_matrix_sync(bf, &Bc[kk * BNP + wn * 32 + nj * 16], BNP);
                    #pragma unroll
                    for (int mi = 0; mi < 4; mi++)
                        wmma::mma_sync(acc[mi][nj], af[mi], bf, acc[mi][nj]);
                }
            }
        }
        __syncthreads();
        cur ^= 1;
    }

    // Epilogue: scale (+ optional tf32 round) + store
    #pragma unroll
    for (int mi = 0; mi < 4; mi++) {
        #pragma unroll
        for (int nj = 0; nj < 2; nj++) {
            #pragma unroll
            for (int e = 0; e < acc[mi][nj].num_elements; e++) {
                float x = acc[mi][nj].x[e] * scale;
                acc[mi][nj].x[e] = ROUND_OUT ? to_tf32(x) : x;
            }
            wmma::store_matrix_sync(
                &C[(long long)(m0 + wm * 64 + mi * 16) * ldc + n0 + wn * 32 + nj * 16],
                acc[mi][nj], ldc, wmma::mem_row_major);
        }
    }
}

// ---------------------------------------------------------------------------
// Elementwise tf32 rounding pass (float4, grid-stride)
// ---------------------------------------------------------------------------
__global__ __launch_bounds__(256)
void cvt_tf32(const float4* __restrict__ in, float4* __restrict__ out, int n4)
{
    for (int i = blockIdx.x * blockDim.x + threadIdx.x; i < n4;
         i += gridDim.x * blockDim.x) {
        float4 v = in[i];
        v.x = to_tf32(v.x); v.y = to_tf32(v.y);
        v.z = to_tf32(v.z); v.w = to_tf32(v.w);
        out[i] = v;
    }
}

// ---------------------------------------------------------------------------
// Row softmax over 2048-wide rows; output rounded to tf32 (feeds P@V GEMM).
// ---------------------------------------------------------------------------
__global__ __launch_bounds__(256)
void softmax2048(float* __restrict__ S)
{
    float* p = S + (long long)blockIdx.x * SEQ;
    const int t = threadIdx.x;

    float4 v0 = *(const float4*)&p[t * 4];
    float4 v1 = *(const float4*)&p[1024 + t * 4];

    float m = fmaxf(fmaxf(fmaxf(v0.x, v0.y), fmaxf(v0.z, v0.w)),
                    fmaxf(fmaxf(v1.x, v1.y), fmaxf(v1.z, v1.w)));
    #pragma unroll
    for (int o = 16; o > 0; o >>= 1)
        m = fmaxf(m, __shfl_xor_sync(0xffffffffu, m, o));

    __shared__ float sm[8], ss[8];
    if ((t & 31) == 0) sm[t >> 5] = m;
    __syncthreads();
    m = fmaxf(fmaxf(fmaxf(sm[0], sm[1]), fmaxf(sm[2], sm[3])),
              fmaxf(fmaxf(sm[4], sm[5]), fmaxf(sm[6], sm[7])));

    v0.x = __expf(v0.x - m); v0.y = __expf(v0.y - m);
    v0.z = __expf(v0.z - m); v0.w = __expf(v0.w - m);
    v1.x = __expf(v1.x - m); v1.y = __expf(v1.y - m);
    v1.z = __expf(v1.z - m); v1.w = __expf(v1.w - m);

    float s = (v0.x + v0.y + v0.z + v0.w) + (v1.x + v1.y + v1.z + v1.w);
    #pragma unroll
    for (int o = 16; o > 0; o >>= 1)
        s += __shfl_xor_sync(0xffffffffu, s, o);
    if ((t & 31) == 0) ss[t >> 5] = s;
    __syncthreads();
    s = (ss[0] + ss[1] + ss[2] + ss[3]) + (ss[4] + ss[5] + ss[6] + ss[7]);

    float inv = 1.0f / s;
    v0.x = to_tf32(v0.x * inv); v0.y = to_tf32(v0.y * inv);
    v0.z = to_tf32(v0.z * inv); v0.w = to_tf32(v0.w * inv);
    v1.x = to_tf32(v1.x * inv); v1.y = to_tf32(v1.y * inv);
    v1.z = to_tf32(v1.z * inv); v1.w = to_tf32(v1.w * inv);

    *(float4*)&p[t * 4]        = v0;
    *(float4*)&p[1024 + t * 4] = v1;
}

// ---------------------------------------------------------------------------
extern "C" void kernel_launch(void* const* d_in, const int* in_sizes, int n_in,
                              void* d_out, int out_size)
{
    const float* X  = (const float*)d_in[0];
    const float* Wq = (const float*)d_in[1];
    const float* bq = (const float*)d_in[2];
    const float* Wk = (const float*)d_in[3];
    const float* bk = (const float*)d_in[4];
    const float* Wv = (const float*)d_in[5];
    const float* bv = (const float*)d_in[6];
    float* out = (float*)d_out;

    float *q, *k, *v, *s;
    cudaGetSymbolAddress((void**)&q, g_q);
    cudaGetSymbolAddress((void**)&k, g_k);
    cudaGetSymbolAddress((void**)&v, g_v);
    cudaGetSymbolAddress((void**)&s, g_s);

    // Opt-in smem (idempotent)
    cudaFuncSetAttribute(gemm_tf32<false, true>,
                         cudaFuncAttributeMaxDynamicSharedMemorySize, SMEM_BYTES);
    cudaFuncSetAttribute(gemm_tf32<true, false>,
                         cudaFuncAttributeMaxDynamicSharedMemorySize, SMEM_BYTES);
    cudaFuncSetAttribute(gemm_tf32<false, false>,
                         cudaFuncAttributeMaxDynamicSharedMemorySize, SMEM_BYTES);

    const long long TD = (long long)SEQ * DIM;   // 2097152
    const long long TT = (long long)SEQ * SEQ;   // 4194304

    // Scratch layout inside g_s while phase1 runs (overwritten by scores later):
    float* Xc  = s;                          // 16M floats
    float* Wqc = s + (long long)MTOT * DIM;  // 1M floats
    float* Wkc = Wqc + DIM * DIM;
    float* Wvc = Wkc + DIM * DIM;

    // Phase 0: pre-round inputs to tf32 (removes cvt from GEMM mainloops)
    cvt_tf32<<<4096, 256>>>((const float4*)X,  (float4*)Xc,  MTOT * DIM / 4);
    cvt_tf32<<<1024, 256>>>((const float4*)Wq, (float4*)Wqc, DIM * DIM / 4);
    cvt_tf32<<<1024, 256>>>((const float4*)Wk, (float4*)Wkc, DIM * DIM / 4);
    cvt_tf32<<<1024, 256>>>((const float4*)Wv, (float4*)Wvc, DIM * DIM / 4);

    // Phase 1: Q/K/V projections (outputs rounded to tf32 for next GEMMs)
    {
        dim3 grid(DIM / BN, MTOT / BM, 1);  // (8, 128, 1)
        gemm_tf32<false, true><<<grid, 256, SMEM_BYTES>>>(
            Xc, Wqc, bq, q, DIM, DIM, DIM, DIM, 0, 0, 0, 1.0f);
        gemm_tf32<false, true><<<grid, 256, SMEM_BYTES>>>(
            Xc, Wkc, bk, k, DIM, DIM, DIM, DIM, 0, 0, 0, 1.0f);
        gemm_tf32<false, true><<<grid, 256, SMEM_BYTES>>>(
            Xc, Wvc, bv, v, DIM, DIM, DIM, DIM, 0, 0, 0, 1.0f);
    }

    // Phase 2: scores = (Q @ K^T) / sqrt(D)  (overwrites Xc/Wc region)
    {
        dim3 grid(SEQ / BN, SEQ / BM, BATCH);  // (16, 16, 8)
        gemm_tf32<true, false><<<grid, 256, SMEM_BYTES>>>(
            q, k, nullptr, s, DIM, DIM, DIM, SEQ, TD, TD, TT, 0.03125f);
    }

    // Phase 3: row softmax (writes tf32-rounded P)
    softmax2048<<<MTOT, 256>>>(s);

    // Phase 4: out = P @ V
    {
        dim3 grid(DIM / BN, SEQ / BM, BATCH);  // (8, 16, 8)
        gemm_tf32<false, false><<<grid, 256, SMEM_BYTES>>>(
            s, v, nullptr, out, SEQ, SEQ, DIM, DIM, TT, TD, TD, 1.0f);
    }
}

// round 5
// speedup vs baseline: 6.0793x; 4.2003x over previous
#include <cuda_runtime.h>
#include <cstdint>
#include <cuda_fp16.h>
#include <mma.h>

using namespace nvcuda;

// Problem constants
#define BATCH 8
#define SEQ   2048
#define DIM   1024
#define MTOT  (BATCH * SEQ)        // 16384

// GEMM tiling
#define BM 128
#define BN 128
#define BK 32
#define AKP 40     // A tile row stride in halves (80B, 16B multiple)
#define BKP 40     // B (trans) tile row stride
#define BNP 136    // B (non-trans) tile row stride in halves (272B)
#define BUF_HALVES 5120                    // 128*40, covers all layouts
#define SMEM_BYTES (4 * BUF_HALVES * 2)    // 2xA + 2xB double buffers = 40960 B

// Scratch (__device__ globals; allocation-free rule)
__device__ __half g_q[(long long)MTOT * DIM];        // 32 MB
__device__ __half g_k[(long long)MTOT * DIM];        // 32 MB
__device__ __half g_v[(long long)MTOT * DIM];        // 32 MB
__device__ float  g_s[(long long)BATCH * SEQ * SEQ]; // 128 MB (Xh/Wh, then scores/P)

__device__ __forceinline__ void cp16(void* smem, const void* gmem) {
    unsigned s = (unsigned)__cvta_generic_to_shared(smem);
    asm volatile("cp.async.cg.shared.global [%0], [%1], 16;\n" :: "r"(s), "l"(gmem));
}
#define CP_COMMIT() asm volatile("cp.async.commit_group;\n")

// ---------------------------------------------------------------------------
// FP16 WMMA GEMM (fp32 accumulate), cp.async double-buffered.
//   C[M,N] = scale * (A[M,K] @ B(^T)) (+ bias, HALF_OUT only)
//   TRANSB: B is [N,K] row-major (C = A@B^T); else B is [K,N] row-major.
//   HALF_OUT: C is __half (bias added in epilogue); else C is float.
// ---------------------------------------------------------------------------
template <bool TRANSB, bool HALF_OUT>
__global__ __launch_bounds__(256, 2)
void gemm_fp16(const __half* __restrict__ Ab, const __half* __restrict__ Bb,
               const float* __restrict__ bias, void* __restrict__ Cb,
               int K, int lda, int ldb, int ldc,
               long long sA, long long sB, long long sC, float scale)
{
    extern __shared__ __half sh[];
    __half* As0 = sh;
    __half* As1 = sh + BUF_HALVES;
    __half* Bs0 = sh + 2 * BUF_HALVES;
    __half* Bs1 = sh + 3 * BUF_HALVES;
    __shared__ float epi[8][16 * 20];   // per-warp fp32 staging for half epilogue
    __shared__ float biasS[BN];

    const __half* A = Ab + (long long)blockIdx.z * sA;
    const __half* B = Bb + (long long)blockIdx.z * sB;

    const int m0 = blockIdx.y * BM;
    const int n0 = blockIdx.x * BN;
    const int t  = threadIdx.x;
    const int warp = t >> 5;
    const int lid  = t & 31;
    const int wm = warp >> 2;   // 0..1 (64-row slab)
    const int wn = warp & 3;    // 0..3 (32-col slab)

    if (HALF_OUT && t < BN) biasS[t] = bias ? bias[n0 + t] : 0.0f;

    wmma::fragment<wmma::accumulator, 16, 16, 16, float> acc[4][2];
    #pragma unroll
    for (int mi = 0; mi < 4; mi++)
        #pragma unroll
        for (int nj = 0; nj < 2; nj++)
            wmma::fill_fragment(acc[mi][nj], 0.0f);

    // Stage one K=32 chunk: A 128x32 halves, B 128x32 (trans) or 32x128
    auto stage = [&](int k0, __half* Ad, __half* Bd) {
        #pragma unroll
        for (int j = 0; j < 2; j++) {
            int idx = t + 256 * j;         // 0..511
            int r  = idx >> 2;             // 0..127
            int c8 = (idx & 3) << 3;       // 0,8,16,24
            cp16(&Ad[r * AKP + c8], &A[(long long)(m0 + r) * lda + k0 + c8]);
        }
        if (TRANSB) {
            #pragma unroll
            for (int j = 0; j < 2; j++) {
                int idx = t + 256 * j;
                int r  = idx >> 2;
                int c8 = (idx & 3) << 3;
                cp16(&Bd[r * BKP + c8], &B[(long long)(n0 + r) * ldb + k0 + c8]);
            }
        } else {
            #pragma unroll
            for (int j = 0; j < 2; j++) {
                int idx = t + 256 * j;
                int r  = idx >> 4;             // 0..31
                int c8 = (idx & 15) << 3;      // 0..120
                cp16(&Bd[r * BNP + c8], &B[(long long)(k0 + r) * ldb + n0 + c8]);
            }
        }
        CP_COMMIT();
    };

    const int nchunk = K / BK;
    stage(0, As0, Bs0);

    int cur = 0;
    for (int i = 0; i < nchunk; i++) {
        __half* Ac = cur ? As1 : As0;
        __half* Bc = cur ? Bs1 : Bs0;
        if (i + 1 < nchunk) {
            stage((i + 1) * BK, cur ? As0 : As1, cur ? Bs0 : Bs1);
            asm volatile("cp.async.wait_group 1;\n");
        } else {
            asm volatile("cp.async.wait_group 0;\n");
        }
        __syncthreads();

        #pragma unroll
        for (int kk = 0; kk < BK; kk += 16) {
            wmma::fragment<wmma::matrix_a, 16, 16, 16, __half, wmma::row_major> af[4];
            #pragma unroll
            for (int mi = 0; mi < 4; mi++)
                wmma::load_matrix_sync(af[mi], &Ac[(wm * 64 + mi * 16) * AKP + kk], AKP);

            #pragma unroll
            for (int nj = 0; nj < 2; nj++) {
                if constexpr (TRANSB) {
                    wmma::fragment<wmma::matrix_b, 16, 16, 16, __half,
                                   wmma::col_major> bf;
                    wmma::load_matrix_sync(bf, &Bc[(wn * 32 + nj * 16) * BKP + kk], BKP);
                    #pragma unroll
                    for (int mi = 0; mi < 4; mi++)
                        wmma::mma_sync(acc[mi][nj], af[mi], bf, acc[mi][nj]);
                } else {
                    wmma::fragment<wmma::matrix_b, 16, 16, 16, __half,
                                   wmma::row_major> bf;
                    wmma::load_matrix_sync(bf, &Bc[kk * BNP + wn * 32 + nj * 16], BNP);
                    #pragma unroll
                    for (int mi = 0; mi < 4; mi++)
                        wmma::mma_sync(acc[mi][nj], af[mi], bf, acc[mi][nj]);
                }
            }
        }
        __syncthreads();
        cur ^= 1;
    }

    // Epilogue
    if constexpr (!HALF_OUT) {
        float* C = (float*)Cb + (long long)blockIdx.z * sC;
        #pragma unroll
        for (int mi = 0; mi < 4; mi++)
            #pragma unroll
            for (int nj = 0; nj < 2; nj++) {
                if (scale != 1.0f) {
                    #pragma unroll
                    for (int e = 0; e < acc[mi][nj].num_elements; e++)
                        acc[mi][nj].x[e] *= scale;
                }
                wmma::store_matrix_sync(
                    &C[(long long)(m0 + wm * 64 + mi * 16) * ldc + n0 + wn * 32 + nj * 16],
                    acc[mi][nj], ldc, wmma::mem_row_major);
            }
    } else {
        __half* C = (__half*)Cb + (long long)blockIdx.z * sC;
        float* ep = epi[warp];
        const int r  = lid >> 1;          // 0..15
        const int ch = (lid & 1) * 8;     // 0 or 8
        #pragma unroll
        for (int mi = 0; mi < 4; mi++)
            #pragma unroll
            for (int nj = 0; nj < 2; nj++) {
                wmma::store_matrix_sync(ep, acc[mi][nj], 20, wmma::mem_row_major);
                __syncwarp();
                const int colb = wn * 32 + nj * 16 + ch;
                __half h[8];
                #pragma unroll
                for (int i = 0; i < 8; i++)
                    h[i] = __float2half_rn(ep[r * 20 + ch + i] + biasS[colb + i]);
                *(uint4*)&C[(long long)(m0 + wm * 64 + mi * 16 + r) * ldc + n0 + colb] =
                    *(uint4*)h;
                __syncwarp();
            }
    }
}

// ---------------------------------------------------------------------------
// float -> half conversion (8 elems/thread, grid-stride)
// ---------------------------------------------------------------------------
__global__ __launch_bounds__(256)
void cvt_f2h(const float4* __restrict__ in, uint4* __restrict__ out, int n8)
{
    for (int i = blockIdx.x * blockDim.x + threadIdx.x; i < n8;
         i += gridDim.x * blockDim.x) {
        float4 a = in[i * 2], b = in[i * 2 + 1];
        __half h[8];
        h[0] = __float2half_rn(a.x); h[1] = __float2half_rn(a.y);
        h[2] = __float2half_rn(a.z); h[3] = __float2half_rn(a.w);
        h[4] = __float2half_rn(b.x); h[5] = __float2half_rn(b.y);
        h[6] = __float2half_rn(b.z); h[7] = __float2half_rn(b.w);
        out[i] = *(uint4*)h;
    }
}

// ---------------------------------------------------------------------------
// Row softmax over 2048 fp32 scores; writes 2048 halves IN PLACE (row head).
// Safe: block-wide reduction barriers order all reads before any write.
// ---------------------------------------------------------------------------
__global__ __launch_bounds__(256)
void softmax2048(float* __restrict__ S)
{
    float* p = S + (long long)blockIdx.x * SEQ;
    const int t = threadIdx.x;

    float4 v0 = *(const float4*)&p[t * 4];
    float4 v1 = *(const float4*)&p[1024 + t * 4];

    float m = fmaxf(fmaxf(fmaxf(v0.x, v0.y), fmaxf(v0.z, v0.w)),
                    fmaxf(fmaxf(v1.x, v1.y), fmaxf(v1.z, v1.w)));
    #pragma unroll
    for (int o = 16; o > 0; o >>= 1)
        m = fmaxf(m, __shfl_xor_sync(0xffffffffu, m, o));

    __shared__ float sm[8], ss[8];
    if ((t & 31) == 0) sm[t >> 5] = m;
    __syncthreads();
    m = fmaxf(fmaxf(fmaxf(sm[0], sm[1]), fmaxf(sm[2], sm[3])),
              fmaxf(fmaxf(sm[4], sm[5]), fmaxf(sm[6], sm[7])));

    v0.x = __expf(v0.x - m); v0.y = __expf(v0.y - m);
    v0.z = __expf(v0.z - m); v0.w = __expf(v0.w - m);
    v1.x = __expf(v1.x - m); v1.y = __expf(v1.y - m);
    v1.z = __expf(v1.z - m); v1.w = __expf(v1.w - m);

    float s = (v0.x + v0.y + v0.z + v0.w) + (v1.x + v1.y + v1.z + v1.w);
    #pragma unroll
    for (int o = 16; o > 0; o >>= 1)
        s += __shfl_xor_sync(0xffffffffu, s, o);
    if ((t & 31) == 0) ss[t >> 5] = s;
    __syncthreads();
    s = (ss[0] + ss[1] + ss[2] + ss[3]) + (ss[4] + ss[5] + ss[6] + ss[7]);

    float inv = 1.0f / s;
    __half* ph = (__half*)p;
    __half h0[4], h1[4];
    h0[0] = __float2half_rn(v0.x * inv); h0[1] = __float2half_rn(v0.y * inv);
    h0[2] = __float2half_rn(v0.z * inv); h0[3] = __float2half_rn(v0.w * inv);
    h1[0] = __float2half_rn(v1.x * inv); h1[1] = __float2half_rn(v1.y * inv);
    h1[2] = __float2half_rn(v1.z * inv); h1[3] = __float2half_rn(v1.w * inv);
    *(uint2*)&ph[t * 4]        = *(uint2*)h0;
    *(uint2*)&ph[1024 + t * 4] = *(uint2*)h1;
}

// ---------------------------------------------------------------------------
extern "C" void kernel_launch(void* const* d_in, const int* in_sizes, int n_in,
                              void* d_out, int out_size)
{
    const float* X  = (const float*)d_in[0];
    const float* Wq = (const float*)d_in[1];
    const float* bq = (const float*)d_in[2];
    const float* Wk = (const float*)d_in[3];
    const float* bk = (const float*)d_in[4];
    const float* Wv = (const float*)d_in[5];
    const float* bv = (const float*)d_in[6];
    float* out = (float*)d_out;

    __half *q, *k, *v;
    float* s;
    cudaGetSymbolAddress((void**)&q, g_q);
    cudaGetSymbolAddress((void**)&k, g_k);
    cudaGetSymbolAddress((void**)&v, g_v);
    cudaGetSymbolAddress((void**)&s, g_s);

    cudaFuncSetAttribute(gemm_fp16<false, true>,
                         cudaFuncAttributeMaxDynamicSharedMemorySize, SMEM_BYTES);
    cudaFuncSetAttribute(gemm_fp16<true, false>,
                         cudaFuncAttributeMaxDynamicSharedMemorySize, SMEM_BYTES);
    cudaFuncSetAttribute(gemm_fp16<false, false>,
                         cudaFuncAttributeMaxDynamicSharedMemorySize, SMEM_BYTES);

    const long long TD = (long long)SEQ * DIM;   // 2097152
    const long long TT = (long long)SEQ * SEQ;   // 4194304

    // Half scratch living inside g_s until phase 2 overwrites it:
    __half* Xh  = (__half*)s;                                  // 16M halves
    __half* Wqh = (__half*)(s + (long long)MTOT * DIM / 2);    // +1M halves each
    __half* Wkh = Wqh + (long long)DIM * DIM;
    __half* Wvh = Wkh + (long long)DIM * DIM;

    // Phase 0: convert inputs to half
    cvt_f2h<<<2048, 256>>>((const float4*)X,  (uint4*)Xh,  MTOT * DIM / 8);
    cvt_f2h<<<512, 256>>>((const float4*)Wq, (uint4*)Wqh, DIM * DIM / 8);
    cvt_f2h<<<512, 256>>>((const float4*)Wk, (uint4*)Wkh, DIM * DIM / 8);
    cvt_f2h<<<512, 256>>>((const float4*)Wv, (uint4*)Wvh, DIM * DIM / 8);

    // Phase 1: projections -> half Q/K/V
    {
        dim3 grid(DIM / BN, MTOT / BM, 1);  // (8, 128)
        gemm_fp16<false, true><<<grid, 256, SMEM_BYTES>>>(
            Xh, Wqh, bq, q, DIM, DIM, DIM, DIM, 0, 0, 0, 1.0f);
        gemm_fp16<false, true><<<grid, 256, SMEM_BYTES>>>(
            Xh, Wkh, bk, k, DIM, DIM, DIM, DIM, 0, 0, 0, 1.0f);
        gemm_fp16<false, true><<<grid, 256, SMEM_BYTES>>>(
            Xh, Wvh, bv, v, DIM, DIM, DIM, DIM, 0, 0, 0, 1.0f);
    }

    // Phase 2: scores = (Q @ K^T) / 32  (fp32, overwrites Xh/Wh region)
    {
        dim3 grid(SEQ / BN, SEQ / BM, BATCH);  // (16, 16, 8)
        gemm_fp16<true, false><<<grid, 256, SMEM_BYTES>>>(
            q, k, nullptr, s, DIM, DIM, DIM, SEQ, TD, TD, TT, 0.03125f);
    }

    // Phase 3: softmax; P written as half in place (row stride 2*SEQ halves)
    softmax2048<<<MTOT, 256>>>(s);

    // Phase 4: out = P @ V  (A = half P with lda = 2*SEQ halves)
    {
        dim3 grid(DIM / BN, SEQ / BM, BATCH);  // (8, 16, 8)
        gemm_fp16<false, false><<<grid, 256, SMEM_BYTES>>>(
            (const __half*)s, v, nullptr, out, SEQ, 2 * SEQ, DIM, DIM,
            2 * TT, TD, TD, 1.0f);
    }
}